// round 1
// baseline (speedup 1.0000x reference)
#include <cuda_runtime.h>
#include <cuda_bf16.h>
#include <cstdint>

// Problem constants
#define DIMC   512
#define NHEAD  16
#define HD     32
#define NTOK   64          // window size 8x8
#define NB     1024        // number of windows
#define NROWS  (NB * NTOK) // 65536 rows
#define QKVC   (3 * DIMC)  // 1536

// ---------------------------------------------------------------------------
// Scratch (static device allocations — no cudaMalloc allowed)
// ---------------------------------------------------------------------------
__device__ float g_qkv[(size_t)NROWS * QKVC];   // 402 MB: qkv = x @ Wqkv^T + b
__device__ float g_att[(size_t)NROWS * DIMC];   // 134 MB: attention output
__device__ float g_bs[2 * NHEAD * NTOK * NTOK]; // rel bias + rel scale, expanded

// ---------------------------------------------------------------------------
// Kernel 0: expand relative_table via relative_index into per-head bias/scale
// g_bs[0      .. 65535] = bias [h][i*64+j]
// g_bs[65536 .. 131071] = scale[h][i*64+j]
// ---------------------------------------------------------------------------
__global__ void bs_expand_kernel(const float* __restrict__ table,
                                 const int* __restrict__ ridx,
                                 float* __restrict__ bs)
{
    int t = blockIdx.x * blockDim.x + threadIdx.x;  // 0 .. 65535
    int h  = t >> 12;      // / 4096
    int ij = t & 4095;
    int idx = ridx[ij];
    bs[t]                     = table[idx * (2 * NHEAD) + h];
    bs[NHEAD * 4096 + t]      = table[idx * (2 * NHEAD) + NHEAD + h];
}

// ---------------------------------------------------------------------------
// SGEMM: C[M,N] = A[M,K] @ W[N,K]^T + bias[N]
// 128x128 block tile, BK=8, 256 threads, 8x8 per-thread micro-tile,
// float4 global loads with register prefetch (single-stage smem).
// Requires: M%128==0, N%128==0, K%8==0, K%4==0 alignment (K=512 here).
// ---------------------------------------------------------------------------
__global__ __launch_bounds__(256) void sgemm_bias(const float* __restrict__ A,
                                                  const float* __restrict__ W,
                                                  const float* __restrict__ bias,
                                                  float* __restrict__ C,
                                                  int M, int N, int K)
{
    __shared__ float As[8][128];
    __shared__ float Bs[8][128];

    const int tid = threadIdx.x;
    const int m0 = blockIdx.x * 128;
    const int n0 = blockIdx.y * 128;
    const int tx = tid & 15;      // 0..15 -> N direction
    const int ty = tid >> 4;      // 0..15 -> M direction

    // global-load assignment: one float4 per thread per tile
    const int lr = tid >> 1;            // 0..127
    const int lc = (tid & 1) * 4;       // 0 or 4
    const float* Aptr = A + (size_t)(m0 + lr) * K + lc;
    const float* Wptr = W + (size_t)(n0 + lr) * K + lc;

    float4 a_next = *(const float4*)Aptr;
    float4 w_next = *(const float4*)Wptr;

    float acc[8][8];
    #pragma unroll
    for (int i = 0; i < 8; ++i)
        #pragma unroll
        for (int j = 0; j < 8; ++j) acc[i][j] = 0.f;

    const int ktiles = K >> 3;
    for (int t = 0; t < ktiles; ++t) {
        // stage into smem (transposed: [k][m] / [k][n])
        As[lc + 0][lr] = a_next.x; As[lc + 1][lr] = a_next.y;
        As[lc + 2][lr] = a_next.z; As[lc + 3][lr] = a_next.w;
        Bs[lc + 0][lr] = w_next.x; Bs[lc + 1][lr] = w_next.y;
        Bs[lc + 2][lr] = w_next.z; Bs[lc + 3][lr] = w_next.w;
        __syncthreads();

        if (t + 1 < ktiles) {
            a_next = *(const float4*)(Aptr + (size_t)(t + 1) * 8);
            w_next = *(const float4*)(Wptr + (size_t)(t + 1) * 8);
        }

        #pragma unroll
        for (int kk = 0; kk < 8; ++kk) {
            float4 a0 = *(const float4*)(&As[kk][ty * 8]);
            float4 a1 = *(const float4*)(&As[kk][ty * 8 + 4]);
            float4 b0 = *(const float4*)(&Bs[kk][tx * 8]);
            float4 b1 = *(const float4*)(&Bs[kk][tx * 8 + 4]);
            float ar[8] = {a0.x, a0.y, a0.z, a0.w, a1.x, a1.y, a1.z, a1.w};
            float br[8] = {b0.x, b0.y, b0.z, b0.w, b1.x, b1.y, b1.z, b1.w};
            #pragma unroll
            for (int i = 0; i < 8; ++i)
                #pragma unroll
                for (int j = 0; j < 8; ++j)
                    acc[i][j] = fmaf(ar[i], br[j], acc[i][j]);
        }
        __syncthreads();
    }

    // epilogue: + bias, vectorized stores
    float4 bia0 = *(const float4*)(bias + n0 + tx * 8);
    float4 bia1 = *(const float4*)(bias + n0 + tx * 8 + 4);
    #pragma unroll
    for (int i = 0; i < 8; ++i) {
        int row = m0 + ty * 8 + i;
        float* crow = C + (size_t)row * N + n0 + tx * 8;
        float4 o0 = make_float4(acc[i][0] + bia0.x, acc[i][1] + bia0.y,
                                acc[i][2] + bia0.z, acc[i][3] + bia0.w);
        float4 o1 = make_float4(acc[i][4] + bia1.x, acc[i][5] + bia1.y,
                                acc[i][6] + bia1.z, acc[i][7] + bia1.w);
        *(float4*)(crow)     = o0;
        *(float4*)(crow + 4) = o1;
    }
}

// ---------------------------------------------------------------------------
// Attention kernel: one block per (window b, head h). 256 threads = 8 warps.
// Q,K,V tiles [64,32] in smem (padded). Each warp owns 8 query rows; each lane
// owns 2 key columns for scores and 1 head-dim column for the AV product.
// attn = softmax(q*scale @ k^T + bias) * rel_scale;  out = attn @ v
// ---------------------------------------------------------------------------
__global__ __launch_bounds__(256) void attn_kernel(const float* __restrict__ qkv,
                                                   const float* __restrict__ bs,
                                                   float* __restrict__ att)
{
    __shared__ float Qs[NTOK * 33];
    __shared__ float Ks[NTOK * 33];
    __shared__ float Vs[NTOK * 33];
    __shared__ float P[8][64];

    const int b = blockIdx.x >> 4;
    const int h = blockIdx.x & 15;
    const int tid = threadIdx.x;

    const float* base = qkv + (size_t)b * NTOK * QKVC + h * HD;
    for (int e = tid; e < NTOK * HD; e += 256) {
        int m = e >> 5;
        int d = e & 31;
        const float* row = base + (size_t)m * QKVC;
        Qs[m * 33 + d] = row[d];
        Ks[m * 33 + d] = row[DIMC + d];
        Vs[m * 33 + d] = row[2 * DIMC + d];
    }
    __syncthreads();

    const int w = tid >> 5;
    const int l = tid & 31;
    const float* Bi = bs + h * 4096;
    const float* Sc = bs + NHEAD * 4096 + h * 4096;
    const float scl = 0.17677669529663687f;  // 1/sqrt(32)

    for (int r = w; r < NTOK; r += 8) {
        // scores for key columns m0 = l, m1 = l+32
        float s0 = 0.f, s1 = 0.f;
        const float* qrow = &Qs[r * 33];
        const float* k0 = &Ks[l * 33];
        const float* k1 = &Ks[(l + 32) * 33];
        #pragma unroll
        for (int d = 0; d < 32; ++d) {
            float qd = qrow[d];
            s0 = fmaf(qd, k0[d], s0);
            s1 = fmaf(qd, k1[d], s1);
        }
        s0 = fmaf(s0, scl, Bi[r * 64 + l]);
        s1 = fmaf(s1, scl, Bi[r * 64 + l + 32]);

        // softmax over 64 values (2 per lane)
        float mx = fmaxf(s0, s1);
        #pragma unroll
        for (int o = 16; o > 0; o >>= 1)
            mx = fmaxf(mx, __shfl_xor_sync(0xffffffffu, mx, o));
        float e0 = __expf(s0 - mx);
        float e1 = __expf(s1 - mx);
        float sm = e0 + e1;
        #pragma unroll
        for (int o = 16; o > 0; o >>= 1)
            sm += __shfl_xor_sync(0xffffffffu, sm, o);
        float inv = __fdividef(1.f, sm);

        P[w][l]      = e0 * inv * Sc[r * 64 + l];
        P[w][l + 32] = e1 * inv * Sc[r * 64 + l + 32];
        __syncwarp();

        // out[r][d=l] = sum_m P[m] * V[m][l]
        float acc = 0.f;
        #pragma unroll
        for (int m = 0; m < 64; ++m)
            acc = fmaf(P[w][m], Vs[m * 33 + l], acc);

        att[((size_t)(b * NTOK + r)) * DIMC + h * HD + l] = acc;
        __syncwarp();  // protect P before next row overwrites
    }
}

// ---------------------------------------------------------------------------
// Launch
// ---------------------------------------------------------------------------
extern "C" void kernel_launch(void* const* d_in, const int* in_sizes, int n_in,
                              void* d_out, int out_size)
{
    const float* x       = (const float*)d_in[0];
    const float* qkv_w   = (const float*)d_in[1];
    const float* qkv_b   = (const float*)d_in[2];
    const float* proj_w  = (const float*)d_in[3];
    const float* proj_b  = (const float*)d_in[4];
    const float* table   = (const float*)d_in[5];
    const int*   rel_idx = (const int*)d_in[6];
    float* out = (float*)d_out;

    float *p_qkv, *p_att, *p_bs;
    cudaGetSymbolAddress((void**)&p_qkv, g_qkv);
    cudaGetSymbolAddress((void**)&p_att, g_att);
    cudaGetSymbolAddress((void**)&p_bs,  g_bs);

    // 0) expand relative bias/scale tables
    bs_expand_kernel<<<(NHEAD * 4096) / 256, 256>>>(table, rel_idx, p_bs);

    // 1) qkv = x @ Wqkv^T + b      (65536 x 1536, K=512)
    sgemm_bias<<<dim3(NROWS / 128, QKVC / 128), 256>>>(
        x, qkv_w, qkv_b, p_qkv, NROWS, QKVC, DIMC);

    // 2) windowed attention per (b, h)
    attn_kernel<<<NB * NHEAD, 256>>>(p_qkv, p_bs, p_att);

    // 3) out = att @ Wproj^T + b   (65536 x 512, K=512)
    sgemm_bias<<<dim3(NROWS / 128, DIMC / 128), 256>>>(
        p_att, proj_w, proj_b, out, NROWS, DIMC, DIMC);
}

// round 3
// speedup vs baseline: 1.8323x; 1.8323x over previous
#include <cuda_runtime.h>
#include <cuda_bf16.h>
#include <cstdint>

// Problem constants
#define DIMC   512
#define NHEAD  16
#define HD     32
#define NTOK   64
#define NB     1024
#define NROWS  (NB * NTOK)   // 65536
#define QKVC   (3 * DIMC)    // 1536

// ---------------------------------------------------------------------------
// Scratch
// ---------------------------------------------------------------------------
__device__ float g_qkv[(size_t)NROWS * QKVC];
__device__ float g_att[(size_t)NROWS * DIMC];
__device__ float g_bs[2 * NHEAD * NTOK * NTOK];

// ---------------------------------------------------------------------------
// helpers
// ---------------------------------------------------------------------------
__device__ __forceinline__ uint32_t smem_u32(const void* p) {
    uint32_t a;
    asm("{ .reg .u64 t; cvta.to.shared.u64 t, %1; cvt.u32.u64 %0, t; }"
        : "=r"(a) : "l"(p));
    return a;
}

__device__ __forceinline__ void ldm_x4(uint32_t& r0, uint32_t& r1,
                                       uint32_t& r2, uint32_t& r3, uint32_t addr) {
    asm volatile("ldmatrix.sync.aligned.m8n8.x4.shared.b16 {%0,%1,%2,%3}, [%4];"
                 : "=r"(r0), "=r"(r1), "=r"(r2), "=r"(r3) : "r"(addr));
}

__device__ __forceinline__ void mma_bf16(float* d, const uint32_t* a,
                                         uint32_t b0, uint32_t b1) {
    asm volatile(
        "mma.sync.aligned.m16n8k16.row.col.f32.bf16.bf16.f32 "
        "{%0,%1,%2,%3}, {%4,%5,%6,%7}, {%8,%9}, {%0,%1,%2,%3};"
        : "+f"(d[0]), "+f"(d[1]), "+f"(d[2]), "+f"(d[3])
        : "r"(a[0]), "r"(a[1]), "r"(a[2]), "r"(a[3]), "r"(b0), "r"(b1));
}

// ---------------------------------------------------------------------------
// Kernel 0: expand relative table
// ---------------------------------------------------------------------------
__global__ void bs_expand_kernel(const float* __restrict__ table,
                                 const int* __restrict__ ridx,
                                 float* __restrict__ bs)
{
    int t = blockIdx.x * blockDim.x + threadIdx.x;
    int h  = t >> 12;
    int ij = t & 4095;
    int idx = ridx[ij];
    bs[t]                = table[idx * (2 * NHEAD) + h];
    bs[NHEAD * 4096 + t] = table[idx * (2 * NHEAD) + NHEAD + h];
}

// ---------------------------------------------------------------------------
// Split-bf16 tensor-core GEMM via mma.sync (HMMA):
//   C[M,N] = A[M,K] @ W[N,K]^T + bias[N]   (fp32 in/out)
// A = Ah + Al (bf16 split), 3 passes: Ah*Bh + Ah*Bl + Al*Bh  (fp32 accum)
// Block tile 128x64, KB=32, 256 threads = 8 warps (2M x 4N), warp tile 64x16.
// Smem rows padded to 80B -> conflict-free ldmatrix.
// ---------------------------------------------------------------------------
#define BM 128
#define BN 64
#define KB 32
#define PITCH 80   // bytes per smem row (32 bf16 = 64B + 16B pad)

__global__ __launch_bounds__(256, 2) void gemm_mma(const float* __restrict__ A,
                                                   const float* __restrict__ W,
                                                   const float* __restrict__ bias,
                                                   float* __restrict__ C,
                                                   int M, int N, int K)
{
    __shared__ char sAh[BM * PITCH];
    __shared__ char sAl[BM * PITCH];
    __shared__ char sBh[BN * PITCH];
    __shared__ char sBl[BN * PITCH];

    const int tid = threadIdx.x;
    const int wid = tid >> 5;
    const int lid = tid & 31;
    const int n0 = blockIdx.x * BN;
    const int m0 = blockIdx.y * BM;

    const int wm = wid & 1;        // 0..1 -> M
    const int wn = wid >> 1;       // 0..3 -> N

    const uint32_t uAh = smem_u32(sAh);
    const uint32_t uAl = smem_u32(sAl);
    const uint32_t uBh = smem_u32(sBh);
    const uint32_t uBl = smem_u32(sBl);

    // ldmatrix per-lane address offsets
    const int i4 = lid >> 3;       // matrix index 0..3
    const int r8 = lid & 7;        // row within 8x8
    const uint32_t a_off =
        (uint32_t)((wm * 64 + ((i4 & 1) ? 8 : 0) + r8) * PITCH + ((i4 & 2) ? 16 : 0));
    const uint32_t b_off =
        (uint32_t)((wn * 16 + ((i4 & 2) ? 8 : 0) + r8) * PITCH + ((i4 & 1) ? 16 : 0));

    float acc[4][2][4];
    #pragma unroll
    for (int mi = 0; mi < 4; ++mi)
        #pragma unroll
        for (int ni = 0; ni < 2; ++ni)
            #pragma unroll
            for (int e = 0; e < 4; ++e) acc[mi][ni][e] = 0.f;

    // global load map:  A: q = i*256+tid, row=q>>3 (0..127), c4=q&7 (float4)
    //                   B: q = i*256+tid, row=q>>3 (0..63)
    const float* Abase = A + (size_t)m0 * K;
    const float* Wbase = W + (size_t)n0 * K;
    const int ar = (tid >> 3);               // reused per i with +32 rows
    const int ac4 = (tid & 7);

    float4 ra[4], rb[2];
    #pragma unroll
    for (int i = 0; i < 4; ++i)
        ra[i] = *(const float4*)(Abase + (size_t)(i * 32 + ar) * K + ac4 * 4);
    #pragma unroll
    for (int i = 0; i < 2; ++i)
        rb[i] = *(const float4*)(Wbase + (size_t)(i * 32 + ar) * K + ac4 * 4);

    const int nst = K / KB;   // 16
    for (int s = 0; s < nst; ++s) {
        if (s > 0) __syncthreads();   // all warps done with previous slab

        // split + store to smem
        #pragma unroll
        for (int i = 0; i < 4; ++i) {
            float4 v = ra[i];
            uint32_t off = (uint32_t)((i * 32 + ar) * PITCH + ac4 * 8);
            __nv_bfloat162 h01 = {__float2bfloat16(v.x), __float2bfloat16(v.y)};
            __nv_bfloat162 h23 = {__float2bfloat16(v.z), __float2bfloat16(v.w)};
            __nv_bfloat162 l01 = {__float2bfloat16(v.x - __bfloat162float(h01.x)),
                                  __float2bfloat16(v.y - __bfloat162float(h01.y))};
            __nv_bfloat162 l23 = {__float2bfloat16(v.z - __bfloat162float(h23.x)),
                                  __float2bfloat16(v.w - __bfloat162float(h23.y))};
            uint2 hu = {*(uint32_t*)&h01, *(uint32_t*)&h23};
            uint2 lu = {*(uint32_t*)&l01, *(uint32_t*)&l23};
            *(uint2*)(sAh + off) = hu;
            *(uint2*)(sAl + off) = lu;
        }
        #pragma unroll
        for (int i = 0; i < 2; ++i) {
            float4 v = rb[i];
            uint32_t off = (uint32_t)((i * 32 + ar) * PITCH + ac4 * 8);
            __nv_bfloat162 h01 = {__float2bfloat16(v.x), __float2bfloat16(v.y)};
            __nv_bfloat162 h23 = {__float2bfloat16(v.z), __float2bfloat16(v.w)};
            __nv_bfloat162 l01 = {__float2bfloat16(v.x - __bfloat162float(h01.x)),
                                  __float2bfloat16(v.y - __bfloat162float(h01.y))};
            __nv_bfloat162 l23 = {__float2bfloat16(v.z - __bfloat162float(h23.x)),
                                  __float2bfloat16(v.w - __bfloat162float(h23.y))};
            uint2 hu = {*(uint32_t*)&h01, *(uint32_t*)&h23};
            uint2 lu = {*(uint32_t*)&l01, *(uint32_t*)&l23};
            *(uint2*)(sBh + off) = hu;
            *(uint2*)(sBl + off) = lu;
        }
        __syncthreads();

        // prefetch next slab while tensor pipe works
        if (s + 1 < nst) {
            const int kc = (s + 1) * KB;
            #pragma unroll
            for (int i = 0; i < 4; ++i)
                ra[i] = *(const float4*)(Abase + (size_t)(i * 32 + ar) * K + kc + ac4 * 4);
            #pragma unroll
            for (int i = 0; i < 2; ++i)
                rb[i] = *(const float4*)(Wbase + (size_t)(i * 32 + ar) * K + kc + ac4 * 4);
        }

        // compute: 2 k-steps of 16
        #pragma unroll
        for (int ks = 0; ks < 2; ++ks) {
            uint32_t bh[4], bl[4];
            ldm_x4(bh[0], bh[1], bh[2], bh[3], uBh + b_off + ks * 32);
            ldm_x4(bl[0], bl[1], bl[2], bl[3], uBl + b_off + ks * 32);
            #pragma unroll
            for (int mi = 0; mi < 4; ++mi) {
                uint32_t ah[4], al[4];
                ldm_x4(ah[0], ah[1], ah[2], ah[3],
                       uAh + a_off + mi * (16 * PITCH) + ks * 32);
                ldm_x4(al[0], al[1], al[2], al[3],
                       uAl + a_off + mi * (16 * PITCH) + ks * 32);
                mma_bf16(acc[mi][0], ah, bh[0], bh[1]);
                mma_bf16(acc[mi][0], ah, bl[0], bl[1]);
                mma_bf16(acc[mi][0], al, bh[0], bh[1]);
                mma_bf16(acc[mi][1], ah, bh[2], bh[3]);
                mma_bf16(acc[mi][1], ah, bl[2], bl[3]);
                mma_bf16(acc[mi][1], al, bh[2], bh[3]);
            }
        }
    }

    // epilogue
    const int gid = lid >> 2;
    const int tig = lid & 3;
    #pragma unroll
    for (int mi = 0; mi < 4; ++mi) {
        #pragma unroll
        for (int ni = 0; ni < 2; ++ni) {
            int row = m0 + wm * 64 + mi * 16 + gid;
            int col = n0 + wn * 16 + ni * 8 + 2 * tig;
            float2 bv = *(const float2*)(bias + col);
            float2 o0 = {acc[mi][ni][0] + bv.x, acc[mi][ni][1] + bv.y};
            float2 o1 = {acc[mi][ni][2] + bv.x, acc[mi][ni][3] + bv.y};
            *(float2*)(C + (size_t)row * N + col) = o0;
            *(float2*)(C + (size_t)(row + 8) * N + col) = o1;
        }
    }
}

// ---------------------------------------------------------------------------
// Attention kernel (unchanged)
// ---------------------------------------------------------------------------
__global__ __launch_bounds__(256) void attn_kernel(const float* __restrict__ qkv,
                                                   const float* __restrict__ bs,
                                                   float* __restrict__ att)
{
    __shared__ float Qs[NTOK * 33];
    __shared__ float Ks[NTOK * 33];
    __shared__ float Vs[NTOK * 33];
    __shared__ float P[8][64];

    const int b = blockIdx.x >> 4;
    const int h = blockIdx.x & 15;
    const int tid = threadIdx.x;

    const float* base = qkv + (size_t)b * NTOK * QKVC + h * HD;
    for (int e = tid; e < NTOK * HD; e += 256) {
        int m = e >> 5;
        int d = e & 31;
        const float* row = base + (size_t)m * QKVC;
        Qs[m * 33 + d] = row[d];
        Ks[m * 33 + d] = row[DIMC + d];
        Vs[m * 33 + d] = row[2 * DIMC + d];
    }
    __syncthreads();

    const int w = tid >> 5;
    const int l = tid & 31;
    const float* Bi = bs + h * 4096;
    const float* Sc = bs + NHEAD * 4096 + h * 4096;
    const float scl = 0.17677669529663687f;

    for (int r = w; r < NTOK; r += 8) {
        float s0 = 0.f, s1 = 0.f;
        const float* qrow = &Qs[r * 33];
        const float* k0 = &Ks[l * 33];
        const float* k1 = &Ks[(l + 32) * 33];
        #pragma unroll
        for (int d = 0; d < 32; ++d) {
            float qd = qrow[d];
            s0 = fmaf(qd, k0[d], s0);
            s1 = fmaf(qd, k1[d], s1);
        }
        s0 = fmaf(s0, scl, Bi[r * 64 + l]);
        s1 = fmaf(s1, scl, Bi[r * 64 + l + 32]);

        float mx = fmaxf(s0, s1);
        #pragma unroll
        for (int o = 16; o > 0; o >>= 1)
            mx = fmaxf(mx, __shfl_xor_sync(0xffffffffu, mx, o));
        float e0 = __expf(s0 - mx);
        float e1 = __expf(s1 - mx);
        float sm = e0 + e1;
        #pragma unroll
        for (int o = 16; o > 0; o >>= 1)
            sm += __shfl_xor_sync(0xffffffffu, sm, o);
        float inv = __fdividef(1.f, sm);

        P[w][l]      = e0 * inv * Sc[r * 64 + l];
        P[w][l + 32] = e1 * inv * Sc[r * 64 + l + 32];
        __syncwarp();

        float acc = 0.f;
        #pragma unroll
        for (int m = 0; m < 64; ++m)
            acc = fmaf(P[w][m], Vs[m * 33 + l], acc);

        att[((size_t)(b * NTOK + r)) * DIMC + h * HD + l] = acc;
        __syncwarp();
    }
}

// ---------------------------------------------------------------------------
// Launch
// ---------------------------------------------------------------------------
extern "C" void kernel_launch(void* const* d_in, const int* in_sizes, int n_in,
                              void* d_out, int out_size)
{
    const float* x       = (const float*)d_in[0];
    const float* qkv_w   = (const float*)d_in[1];
    const float* qkv_b   = (const float*)d_in[2];
    const float* proj_w  = (const float*)d_in[3];
    const float* proj_b  = (const float*)d_in[4];
    const float* table   = (const float*)d_in[5];
    const int*   rel_idx = (const int*)d_in[6];
    float* out = (float*)d_out;

    float *p_qkv, *p_att, *p_bs;
    cudaGetSymbolAddress((void**)&p_qkv, g_qkv);
    cudaGetSymbolAddress((void**)&p_att, g_att);
    cudaGetSymbolAddress((void**)&p_bs,  g_bs);

    // 0) expand relative bias/scale tables
    bs_expand_kernel<<<(NHEAD * 4096) / 256, 256>>>(table, rel_idx, p_bs);

    // 1) qkv = x @ Wqkv^T + b   (65536 x 1536, K=512)
    gemm_mma<<<dim3(QKVC / BN, NROWS / BM), 256>>>(
        x, qkv_w, qkv_b, p_qkv, NROWS, QKVC, DIMC);

    // 2) windowed attention per (b, h)
    attn_kernel<<<NB * NHEAD, 256>>>(p_qkv, p_bs, p_att);

    // 3) out = att @ Wproj^T + b   (65536 x 512, K=512)
    gemm_mma<<<dim3(DIMC / BN, NROWS / BM), 256>>>(
        p_att, proj_w, proj_b, out, NROWS, DIMC, DIMC);
}

// round 7
// speedup vs baseline: 2.1365x; 1.1660x over previous
#include <cuda_runtime.h>
#include <cuda_bf16.h>
#include <cstdint>

// Problem constants
#define DIMC   512
#define NHEAD  16
#define HD     32
#define NTOK   64
#define NB     1024
#define NROWS  (NB * NTOK)   // 65536
#define QKVC   (3 * DIMC)    // 1536

// ---------------------------------------------------------------------------
// Scratch
// ---------------------------------------------------------------------------
__device__ float g_qkv[(size_t)NROWS * QKVC];                 // fp32 qkv
__device__ float g_bs[2 * NHEAD * NTOK * NTOK];               // bias/scale
__device__ __nv_bfloat16 g_xh[(size_t)NROWS * DIMC];          // x hi/lo
__device__ __nv_bfloat16 g_xl[(size_t)NROWS * DIMC];
__device__ __nv_bfloat16 g_ath[(size_t)NROWS * DIMC];         // attn out hi/lo
__device__ __nv_bfloat16 g_atl[(size_t)NROWS * DIMC];
__device__ __nv_bfloat16 g_wqh[QKVC * DIMC];                  // qkv W hi/lo
__device__ __nv_bfloat16 g_wql[QKVC * DIMC];
__device__ __nv_bfloat16 g_wph[DIMC * DIMC];                  // proj W hi/lo
__device__ __nv_bfloat16 g_wpl[DIMC * DIMC];

// ---------------------------------------------------------------------------
// helpers
// ---------------------------------------------------------------------------
__device__ __forceinline__ uint32_t smem_u32(const void* p) {
    uint32_t a;
    asm("{ .reg .u64 t; cvta.to.shared.u64 t, %1; cvt.u32.u64 %0, t; }"
        : "=r"(a) : "l"(p));
    return a;
}

__device__ __forceinline__ void ldm_x4(uint32_t& r0, uint32_t& r1,
                                       uint32_t& r2, uint32_t& r3, uint32_t addr) {
    asm volatile("ldmatrix.sync.aligned.m8n8.x4.shared.b16 {%0,%1,%2,%3}, [%4];"
                 : "=r"(r0), "=r"(r1), "=r"(r2), "=r"(r3) : "r"(addr));
}

__device__ __forceinline__ void mma_bf16(float* d, const uint32_t* a,
                                         uint32_t b0, uint32_t b1) {
    asm volatile(
        "mma.sync.aligned.m16n8k16.row.col.f32.bf16.bf16.f32 "
        "{%0,%1,%2,%3}, {%4,%5,%6,%7}, {%8,%9}, {%0,%1,%2,%3};"
        : "+f"(d[0]), "+f"(d[1]), "+f"(d[2]), "+f"(d[3])
        : "r"(a[0]), "r"(a[1]), "r"(a[2]), "r"(a[3]), "r"(b0), "r"(b1));
}

#define CP16(dst, src) \
    asm volatile("cp.async.cg.shared.global [%0], [%1], 16;" \
                 :: "r"(dst), "l"(src) : "memory")
#define CP_COMMIT() asm volatile("cp.async.commit_group;" ::: "memory")
#define CP_WAIT(n)  asm volatile("cp.async.wait_group %0;" :: "n"(n) : "memory")

// ---------------------------------------------------------------------------
// Kernel: fp32 -> bf16 hi/lo split (vectorized)
// ---------------------------------------------------------------------------
__global__ void split_kernel(const float* __restrict__ in,
                             __nv_bfloat16* __restrict__ hi,
                             __nv_bfloat16* __restrict__ lo, int n4)
{
    int i = blockIdx.x * blockDim.x + threadIdx.x;
    if (i >= n4) return;
    float4 v = ((const float4*)in)[i];
    __nv_bfloat162 h01 = {__float2bfloat16(v.x), __float2bfloat16(v.y)};
    __nv_bfloat162 h23 = {__float2bfloat16(v.z), __float2bfloat16(v.w)};
    __nv_bfloat162 l01 = {__float2bfloat16(v.x - __bfloat162float(h01.x)),
                          __float2bfloat16(v.y - __bfloat162float(h01.y))};
    __nv_bfloat162 l23 = {__float2bfloat16(v.z - __bfloat162float(h23.x)),
                          __float2bfloat16(v.w - __bfloat162float(h23.y))};
    uint2 hu = {*(uint32_t*)&h01, *(uint32_t*)&h23};
    uint2 lu = {*(uint32_t*)&l01, *(uint32_t*)&l23};
    ((uint2*)hi)[i] = hu;
    ((uint2*)lo)[i] = lu;
}

// ---------------------------------------------------------------------------
// Kernel 0: expand relative table
// ---------------------------------------------------------------------------
__global__ void bs_expand_kernel(const float* __restrict__ table,
                                 const int* __restrict__ ridx,
                                 float* __restrict__ bs)
{
    int t = blockIdx.x * blockDim.x + threadIdx.x;
    int h  = t >> 12;
    int ij = t & 4095;
    int idx = ridx[ij];
    bs[t]                = table[idx * (2 * NHEAD) + h];
    bs[NHEAD * 4096 + t] = table[idx * (2 * NHEAD) + NHEAD + h];
}

// ---------------------------------------------------------------------------
// Split-bf16 HMMA GEMM, pre-split inputs, cp.async double buffer.
//   C[M,N] = (Ah+Al)[M,K] @ (Bh+Bl)[N,K]^T + bias[N]
// BM=128, BN=128, KB=32. 256 threads = 8 warps (2M x 4N), warp tile 64x32.
// ---------------------------------------------------------------------------
#define BM 128
#define BN 128
#define KB 32
#define PITCH 80
#define SLAB  (128 * PITCH)        // 10240
#define STAGE (4 * SLAB)           // 40960
#define SMEM_TOTAL (2 * STAGE)     // 81920

__global__ __launch_bounds__(256, 2)
void gemm_bf16split(const __nv_bfloat16* __restrict__ Ah,
                    const __nv_bfloat16* __restrict__ Al,
                    const __nv_bfloat16* __restrict__ Bh,
                    const __nv_bfloat16* __restrict__ Bl,
                    const float* __restrict__ bias,
                    float* __restrict__ C,
                    int M, int N, int K)
{
    extern __shared__ char smem[];
    const uint32_t sb = smem_u32(smem);

    const int tid = threadIdx.x;
    const int wid = tid >> 5;
    const int lid = tid & 31;
    const int n0 = blockIdx.x * BN;
    const int m0 = blockIdx.y * BM;
    const int wm = wid & 1;
    const int wn = wid >> 1;

    const int r4  = tid >> 2;      // 0..63
    const int c16 = tid & 3;       // 16B chunk

    const int i4 = lid >> 3;
    const int r8 = lid & 7;
    const uint32_t a_off =
        (uint32_t)((wm * 64 + ((i4 & 1) ? 8 : 0) + r8) * PITCH + ((i4 & 2) ? 16 : 0));
    const uint32_t b_off =
        (uint32_t)((wn * 32 + ((i4 & 2) ? 8 : 0) + r8) * PITCH + ((i4 & 1) ? 16 : 0));

    float acc[4][4][4];
    #pragma unroll
    for (int mi = 0; mi < 4; ++mi)
        #pragma unroll
        for (int ni = 0; ni < 4; ++ni)
            #pragma unroll
            for (int e = 0; e < 4; ++e) acc[mi][ni][e] = 0.f;

    const int nst = K / KB;

    #define ISSUE_STAGE(s, buf)                                               \
    do {                                                                      \
        const int kc = (s) * KB;                                              \
        const uint32_t db = sb + (buf) * STAGE;                               \
        _Pragma("unroll")                                                     \
        for (int hh = 0; hh < 2; ++hh) {                                      \
            const int row = hh * 64 + r4;                                     \
            const uint32_t doff = (uint32_t)(row * PITCH + c16 * 16);         \
            CP16(db + 0 * SLAB + doff, Ah + (size_t)(m0 + row) * K + kc + c16 * 8); \
            CP16(db + 1 * SLAB + doff, Al + (size_t)(m0 + row) * K + kc + c16 * 8); \
            CP16(db + 2 * SLAB + doff, Bh + (size_t)(n0 + row) * K + kc + c16 * 8); \
            CP16(db + 3 * SLAB + doff, Bl + (size_t)(n0 + row) * K + kc + c16 * 8); \
        }                                                                     \
        CP_COMMIT();                                                          \
    } while (0)

    ISSUE_STAGE(0, 0);

    for (int s = 0; s < nst; ++s) {
        if (s + 1 < nst) {
            ISSUE_STAGE(s + 1, (s + 1) & 1);
            CP_WAIT(1);
        } else {
            CP_WAIT(0);
        }
        __syncthreads();

        const uint32_t db = sb + (s & 1) * STAGE;
        const uint32_t uAh = db + 0 * SLAB;
        const uint32_t uAl = db + 1 * SLAB;
        const uint32_t uBh = db + 2 * SLAB;
        const uint32_t uBl = db + 3 * SLAB;

        #pragma unroll
        for (int ks = 0; ks < 2; ++ks) {
            uint32_t bh0[4], bh1[4], bl0[4], bl1[4];
            ldm_x4(bh0[0], bh0[1], bh0[2], bh0[3], uBh + b_off + ks * 32);
            ldm_x4(bh1[0], bh1[1], bh1[2], bh1[3], uBh + b_off + 16 * PITCH + ks * 32);
            ldm_x4(bl0[0], bl0[1], bl0[2], bl0[3], uBl + b_off + ks * 32);
            ldm_x4(bl1[0], bl1[1], bl1[2], bl1[3], uBl + b_off + 16 * PITCH + ks * 32);
            #pragma unroll
            for (int mi = 0; mi < 4; ++mi) {
                uint32_t ah[4], al[4];
                ldm_x4(ah[0], ah[1], ah[2], ah[3],
                       uAh + a_off + mi * (16 * PITCH) + ks * 32);
                ldm_x4(al[0], al[1], al[2], al[3],
                       uAl + a_off + mi * (16 * PITCH) + ks * 32);
                mma_bf16(acc[mi][0], ah, bh0[0], bh0[1]);
                mma_bf16(acc[mi][0], ah, bl0[0], bl0[1]);
                mma_bf16(acc[mi][0], al, bh0[0], bh0[1]);
                mma_bf16(acc[mi][1], ah, bh0[2], bh0[3]);
                mma_bf16(acc[mi][1], ah, bl0[2], bl0[3]);
                mma_bf16(acc[mi][1], al, bh0[2], bh0[3]);
                mma_bf16(acc[mi][2], ah, bh1[0], bh1[1]);
                mma_bf16(acc[mi][2], ah, bl1[0], bl1[1]);
                mma_bf16(acc[mi][2], al, bh1[0], bh1[1]);
                mma_bf16(acc[mi][3], ah, bh1[2], bh1[3]);
                mma_bf16(acc[mi][3], ah, bl1[2], bl1[3]);
                mma_bf16(acc[mi][3], al, bh1[2], bh1[3]);
            }
        }
        __syncthreads();
    }

    // epilogue
    const int gid = lid >> 2;
    const int tig = lid & 3;
    #pragma unroll
    for (int mi = 0; mi < 4; ++mi) {
        #pragma unroll
        for (int ni = 0; ni < 4; ++ni) {
            int row = m0 + wm * 64 + mi * 16 + gid;
            int col = n0 + wn * 32 + ni * 8 + 2 * tig;
            float2 bv = *(const float2*)(bias + col);
            float2 o0 = {acc[mi][ni][0] + bv.x, acc[mi][ni][1] + bv.y};
            float2 o1 = {acc[mi][ni][2] + bv.x, acc[mi][ni][3] + bv.y};
            *(float2*)(C + (size_t)row * N + col) = o0;
            *(float2*)(C + (size_t)(row + 8) * N + col) = o1;
        }
    }
    #undef ISSUE_STAGE
}

// ---------------------------------------------------------------------------
// Attention kernel — K tile cached in registers, outputs split hi/lo bf16.
// One block per (window b, head h); 8 warps, each owns 8 query rows.
// Lane l keeps key columns l and l+32 (32 fp32 regs each) for ALL rows.
// ---------------------------------------------------------------------------
__global__ __launch_bounds__(256) void attn_kernel(const float* __restrict__ qkv,
                                                   const float* __restrict__ bs,
                                                   __nv_bfloat16* __restrict__ ath,
                                                   __nv_bfloat16* __restrict__ atl)
{
    __shared__ float Qs[NTOK * 33];
    __shared__ float Ks[NTOK * 33];
    __shared__ float Vs[NTOK * 33];
    __shared__ float P[8][64];

    const int b = blockIdx.x >> 4;
    const int h = blockIdx.x & 15;
    const int tid = threadIdx.x;

    const float* base = qkv + (size_t)b * NTOK * QKVC + h * HD;
    for (int e = tid; e < NTOK * HD; e += 256) {
        int m = e >> 5;
        int d = e & 31;
        const float* row = base + (size_t)m * QKVC;
        Qs[m * 33 + d] = row[d];
        Ks[m * 33 + d] = row[DIMC + d];
        Vs[m * 33 + d] = row[2 * DIMC + d];
    }
    __syncthreads();

    const int w = tid >> 5;
    const int l = tid & 31;
    const float* Bi = bs + h * 4096;
    const float* Sc = bs + NHEAD * 4096 + h * 4096;
    const float scl = 0.17677669529663687f;

    // cache this lane's two key columns in registers (reused for all 64 rows)
    float kr0[32], kr1[32];
    #pragma unroll
    for (int d = 0; d < 32; ++d) {
        kr0[d] = Ks[l * 33 + d];
        kr1[d] = Ks[(l + 32) * 33 + d];
    }

    for (int r = w; r < NTOK; r += 8) {
        float s0 = 0.f, s1 = 0.f;
        const float* qrow = &Qs[r * 33];
        #pragma unroll
        for (int d = 0; d < 32; ++d) {
            float qd = qrow[d];               // broadcast LDS
            s0 = fmaf(qd, kr0[d], s0);
            s1 = fmaf(qd, kr1[d], s1);
        }
        s0 = fmaf(s0, scl, Bi[r * 64 + l]);
        s1 = fmaf(s1, scl, Bi[r * 64 + l + 32]);

        float mx = fmaxf(s0, s1);
        #pragma unroll
        for (int o = 16; o > 0; o >>= 1)
            mx = fmaxf(mx, __shfl_xor_sync(0xffffffffu, mx, o));
        float e0 = __expf(s0 - mx);
        float e1 = __expf(s1 - mx);
        float sm = e0 + e1;
        #pragma unroll
        for (int o = 16; o > 0; o >>= 1)
            sm += __shfl_xor_sync(0xffffffffu, sm, o);
        float inv = __fdividef(1.f, sm);

        P[w][l]      = e0 * inv * Sc[r * 64 + l];
        P[w][l + 32] = e1 * inv * Sc[r * 64 + l + 32];
        __syncwarp();

        float acc = 0.f;
        #pragma unroll
        for (int m = 0; m < 64; ++m)
            acc = fmaf(P[w][m], Vs[m * 33 + l], acc);

        size_t idx = ((size_t)(b * NTOK + r)) * DIMC + h * HD + l;
        __nv_bfloat16 hb = __float2bfloat16(acc);
        ath[idx] = hb;
        atl[idx] = __float2bfloat16(acc - __bfloat162float(hb));
        __syncwarp();
    }
}

// ---------------------------------------------------------------------------
// Launch
// ---------------------------------------------------------------------------
extern "C" void kernel_launch(void* const* d_in, const int* in_sizes, int n_in,
                              void* d_out, int out_size)
{
    const float* x       = (const float*)d_in[0];
    const float* qkv_w   = (const float*)d_in[1];
    const float* qkv_b   = (const float*)d_in[2];
    const float* proj_w  = (const float*)d_in[3];
    const float* proj_b  = (const float*)d_in[4];
    const float* table   = (const float*)d_in[5];
    const int*   rel_idx = (const int*)d_in[6];
    float* out = (float*)d_out;

    float *p_qkv, *p_bs;
    __nv_bfloat16 *p_xh, *p_xl, *p_ath, *p_atl, *p_wqh, *p_wql, *p_wph, *p_wpl;
    cudaGetSymbolAddress((void**)&p_qkv, g_qkv);
    cudaGetSymbolAddress((void**)&p_bs,  g_bs);
    cudaGetSymbolAddress((void**)&p_xh,  g_xh);
    cudaGetSymbolAddress((void**)&p_xl,  g_xl);
    cudaGetSymbolAddress((void**)&p_ath, g_ath);
    cudaGetSymbolAddress((void**)&p_atl, g_atl);
    cudaGetSymbolAddress((void**)&p_wqh, g_wqh);
    cudaGetSymbolAddress((void**)&p_wql, g_wql);
    cudaGetSymbolAddress((void**)&p_wph, g_wph);
    cudaGetSymbolAddress((void**)&p_wpl, g_wpl);

    cudaFuncSetAttribute(gemm_bf16split,
                         cudaFuncAttributeMaxDynamicSharedMemorySize, SMEM_TOTAL);

    // 0) table expand + input splits
    bs_expand_kernel<<<(NHEAD * 4096) / 256, 256>>>(table, rel_idx, p_bs);
    split_kernel<<<((size_t)NROWS * DIMC / 4 + 255) / 256, 256>>>(
        x, p_xh, p_xl, NROWS * DIMC / 4);
    split_kernel<<<(QKVC * DIMC / 4 + 255) / 256, 256>>>(
        qkv_w, p_wqh, p_wql, QKVC * DIMC / 4);
    split_kernel<<<(DIMC * DIMC / 4 + 255) / 256, 256>>>(
        proj_w, p_wph, p_wpl, DIMC * DIMC / 4);

    // 1) qkv = x @ Wqkv^T + b
    gemm_bf16split<<<dim3(QKVC / BN, NROWS / BM), 256, SMEM_TOTAL>>>(
        p_xh, p_xl, p_wqh, p_wql, qkv_b, p_qkv, NROWS, QKVC, DIMC);

    // 2) windowed attention per (b, h) — writes split bf16
    attn_kernel<<<NB * NHEAD, 256>>>(p_qkv, p_bs, p_ath, p_atl);

    // 3) out = att @ Wproj^T + b
    gemm_bf16split<<<dim3(DIMC / BN, NROWS / BM), 256, SMEM_TOTAL>>>(
        p_ath, p_atl, p_wph, p_wpl, proj_b, out, NROWS, DIMC, DIMC);
}